// round 8
// baseline (speedup 1.0000x reference)
#include <cuda_runtime.h>
#include <cstdint>

#define H 256
#define W 256
#define K 512
#define Z_THRESHOLD 3.0f
#define EPS 1e-08f

// sqrt(0.5 * log2(e)): folded into inverse scales so gauss = exp2(-(dx'^2+dy'^2))
#define SCALE_C 0.84932180028801904f

#define TPB  512              // threads per block == K
#define GRID ((H * W) / TPB)  // 128 blocks (2 rows each), single wave
#define NWARP (TPB / 32)

// Cull threshold: max block alpha < 2^-20 ~ 1e-6 -> skipped gaussian perturbs
// a pixel by < ~6e-5 absolute; rel tolerance is 1e-3.
#define CULL_LOG2 -20.0f

// ---------------------------------------------------------------------------
// Fused kernel. Every block (2 image rows) redundantly:
//   1) computes per-gaussian eff_w + packed params,
//   2) ballot-compacts the M nonzero-weight keys (zeros are identities; keys
//      embed the original index so ordering survives compaction exactly),
//   3) rank sort: each of M threads counts smaller keys (unique keys -> exact
//      stable argsort(-eff_w)) and scatters params to sp[rank],
//   4) CULLS against this block's two rows: upper-bound the exponent by
//      log2(w) - min_row dx'^2; survivors < 2^-20 alpha are dropped with an
//      ORDER-PRESERVING compaction (warp ballot + warp-count scan),
//   5) renders one pixel per thread over the Mc surviving gaussians.
// One wave, one launch.
// ---------------------------------------------------------------------------
__global__ void __launch_bounds__(TPB, 1)
fused_kernel(const float* __restrict__ positions,   // [K,3]
             const float* __restrict__ scales,      // [K,3]
             const float* __restrict__ opacity,     // [K]
             const float* __restrict__ intensity,   // [K]
             const float* __restrict__ z_target,    // [1]
             float* __restrict__ out)               // [H*W]
{
    __shared__ unsigned long long sk[K];  // compacted active keys
    __shared__ float4 up4[K];   // unsorted: isx', -px*isx', isy', -py*isy'
    __shared__ float  uin[K];   // unsorted intensity
    __shared__ float4 sp[K];    // rank-ordered params
    __shared__ float2 swi[K];   // rank-ordered (log2(eff_w), intensity)
    __shared__ float4 csp[K];   // culled (block-local) params
    __shared__ float2 cswi[K];  // culled (log2 w, intensity)
    __shared__ int    warpCnt[NWARP];
    __shared__ int    sCnt;

    const int tid  = threadIdx.x;
    const int lane = tid & 31;
    const int wid  = tid >> 5;

    if (tid == 0) sCnt = 0;

    // ---- prep: per-gaussian weight + packed params (unsorted) ----
    const float zt  = z_target[0];
    const float px  = positions[tid * 3 + 0];
    const float py  = positions[tid * 3 + 1];
    const float pz  = positions[tid * 3 + 2];
    const float isx = __fdividef(SCALE_C, scales[tid * 3 + 0] + EPS);
    const float isy = __fdividef(SCALE_C, scales[tid * 3 + 1] + EPS);
    const float sz  = scales[tid * 3 + 2];

    const float zd = __fdividef(zt - pz, sz + EPS);
    float w = 0.0f;
    if (fabsf(zd) < Z_THRESHOLD) {
        w = opacity[tid] * __expf(-0.5f * zd * zd);
    }

    up4[tid] = make_float4(isx, -px * isx, isy, -py * isy);
    uin[tid] = intensity[tid];
    __syncthreads();   // sCnt=0 + up4/uin visible

    // ---- compaction of nonzero-weight keys (order-free; rank sort follows) ----
    // Ascending uint64 order == descending eff_w, ascending idx on ties
    // (matches stable jnp.argsort(-eff_w); keys unique via embedded idx).
    const bool active = (w > 0.0f);
    unsigned int wb = __float_as_uint(w);   // w >= 0 so bits are monotone
    unsigned long long key =
        ((unsigned long long)(~wb) << 32) | (unsigned int)tid;

    unsigned int mask = __ballot_sync(0xFFFFFFFFu, active);
    int base = 0;
    if (lane == 0 && mask) base = atomicAdd(&sCnt, __popc(mask));
    base = __shfl_sync(0xFFFFFFFFu, base, 0);
    if (active) {
        int pos = base + __popc(mask & ((1u << lane) - 1u));
        sk[pos] = key;
    }
    __syncthreads();

    const int M = sCnt;

    // ---- rank sort: thread t (< M) ranks its compacted key against all M ----
    if (tid < M) {
        const unsigned long long mykey = sk[tid];
        int rank = 0;
        #pragma unroll 4
        for (int j = 0; j < M; ++j) {
            rank += (sk[j] < mykey);   // broadcast LDS, unique keys
        }
        const int src = (int)(mykey & 0xFFFFFFFFull);
        const float ws = __uint_as_float(~(unsigned int)(mykey >> 32));
        sp[rank]  = up4[src];
        swi[rank] = make_float2(__log2f(ws), uin[src]);
    }
    __syncthreads();

    // ---- per-block cull (rows 2b, 2b+1) + order-preserving compaction ----
    const float row0 = (float)(2 * blockIdx.x);
    bool keep = false;
    if (tid < M) {
        const float4 P = sp[tid];
        float a0 = fmaf(row0, P.x, P.y);       // dx' at row 2b
        float a1 = a0 + P.x;                   // dx' at row 2b+1
        float dmin2 = fminf(a0 * a0, a1 * a1); // min over this block's rows
        keep = (swi[tid].x - dmin2 > CULL_LOG2);  // dy'^2 >= 0 bound
    }
    unsigned int kb = __ballot_sync(0xFFFFFFFFu, keep);
    if (lane == 0) warpCnt[wid] = __popc(kb);
    __syncthreads();

    int base2 = 0;
    #pragma unroll
    for (int wi = 0; wi < NWARP; ++wi) {
        int c = warpCnt[wi];
        if (wi < wid) base2 += c;
    }
    if (keep) {
        int pos = base2 + __popc(kb & ((1u << lane) - 1u));
        csp[pos]  = sp[tid];
        cswi[pos] = swi[tid];
    }
    // Total survivor count (every thread sums all warp counts).
    int Mc = 0;
    #pragma unroll
    for (int wi = 0; wi < NWARP; ++wi) Mc += warpCnt[wi];
    __syncthreads();

    // ---- render: one pixel per thread ----
    const int p = blockIdx.x * TPB + tid;
    const float fy = (float)(p >> 8);    // row    (positions[:,0])
    const float fx = (float)(p & 255);   // column (positions[:,1])

    float T = 1.0f;
    float A = 0.0f;

    #pragma unroll 4
    for (int j = 0; j < Mc; ++j) {
        const float4 P  = csp[j];
        const float2 WI = cswi[j];

        float dx  = fmaf(fy, P.x, P.y);        // (fy - px) * isx'
        float dy  = fmaf(fx, P.z, P.w);        // (fx - py) * isy'
        float t0  = fmaf(dx, -dx, WI.x);       // log2(w) - dx'^2
        float arg = fmaf(dy, -dy, t0);         // log2(w) - dx'^2 - dy'^2

        float ga;                              // == gauss * eff_w
        asm("ex2.approx.ftz.f32 %0, %1;" : "=f"(ga) : "f"(arg));

        float a  = fminf(ga, 0.99f);
        float ta = T * a;
        A = fmaf(ta, WI.y, A);
        T -= ta;
    }

    out[p] = A;
}

extern "C" void kernel_launch(void* const* d_in, const int* in_sizes, int n_in,
                              void* d_out, int out_size)
{
    const float* positions = (const float*)d_in[0];
    const float* scales    = (const float*)d_in[1];
    const float* opacity   = (const float*)d_in[2];
    const float* intensity = (const float*)d_in[3];
    const float* z_target  = (const float*)d_in[4];
    float* out = (float*)d_out;

    fused_kernel<<<GRID, TPB>>>(positions, scales, opacity, intensity,
                                z_target, out);
}

// round 9
// speedup vs baseline: 1.3527x; 1.3527x over previous
#include <cuda_runtime.h>
#include <cstdint>

#define H 256
#define W 256
#define K 512
#define Z_THRESHOLD 3.0f
#define EPS 1e-08f

// sqrt(0.5 * log2(e)): folded into inverse scales so gauss = exp2(-(dx'^2+dy'^2))
#define SCALE_C 0.84932180028801904f

#define TPB   256            // threads per block (1 image row per block)
#define GPT   2              // gaussians per thread (K / TPB)
#define GRID  H              // 256 blocks, 2 resident per SM

// Cull threshold: max row alpha < 2^-20 ~ 1e-6 -> skipped gaussian perturbs
// a pixel by < ~6e-5 absolute; rel tolerance is 1e-3.
#define CULL_LOG2 -20.0f

// ---------------------------------------------------------------------------
// Fused kernel, cull-first version. Each block owns ONE image row, so each
// gaussian's dx'^2 is a per-gaussian constant that folds into the exponent.
//   1) prep: each thread computes 2 gaussians' eff_w and row-folded params
//      top = log2(eff_w) - dx'^2 (packed with isy', -py*isy', intensity),
//   2) cull-compact: ballot-compact keys of gaussians with w>0 AND
//      top > CULL_LOG2 (order-free; keys embed original idx),
//   3) rank sort over the ~7 survivors: rank = #{smaller keys} (unique keys
//      -> exact relative order of the stable argsort(-eff_w) restricted to
//      survivors), scatter params to csp[rank],
//   4) render: 1 px/thread, 9-instr inner loop.
// 3 barriers, every loop < ~10 iters, 2 blocks/SM overlap the stalls.
// ---------------------------------------------------------------------------
__global__ void __launch_bounds__(TPB, 2)
fused_kernel(const float* __restrict__ positions,   // [K,3]
             const float* __restrict__ scales,      // [K,3]
             const float* __restrict__ opacity,     // [K]
             const float* __restrict__ intensity,   // [K]
             const float* __restrict__ z_target,    // [1]
             float* __restrict__ out)               // [H*W]
{
    __shared__ float4 up4[K];             // unsorted: isy', -py*isy', top, inten
    __shared__ unsigned long long sk[K];  // compacted survivor keys
    __shared__ float4 csp[K];             // rank-ordered survivor params
    __shared__ int    sCnt;

    const int tid  = threadIdx.x;
    const int lane = tid & 31;
    const float fy = (float)blockIdx.x;   // this block's image row

    if (tid == 0) sCnt = 0;

    // ---- prep + cull test for 2 gaussians per thread ----
    const float zt = z_target[0];
    bool  kp[GPT];
    unsigned long long kk[GPT];

    #pragma unroll
    for (int s = 0; s < GPT; ++s) {
        const int g = tid + s * TPB;
        const float px  = positions[g * 3 + 0];
        const float py  = positions[g * 3 + 1];
        const float pz  = positions[g * 3 + 2];
        const float isx = __fdividef(SCALE_C, scales[g * 3 + 0] + EPS);
        const float isy = __fdividef(SCALE_C, scales[g * 3 + 1] + EPS);
        const float sz  = scales[g * 3 + 2];

        const float zd = __fdividef(zt - pz, sz + EPS);
        float w = 0.0f;
        if (fabsf(zd) < Z_THRESHOLD) {
            w = opacity[g] * __expf(-0.5f * zd * zd);
        }

        float dxp = (fy - px) * isx;                  // row-constant dx'
        float top = __log2f(w) - dxp * dxp;           // folded exponent peak
        kp[s] = (w > 0.0f) && (top > CULL_LOG2);

        // Ascending uint64 order == descending eff_w, ascending idx on ties
        // (stable argsort(-eff_w); keys unique via embedded idx).
        unsigned int wb = __float_as_uint(w);         // w >= 0: bits monotone
        kk[s] = ((unsigned long long)(~wb) << 32) | (unsigned int)g;

        up4[g] = make_float4(isy, -py * isy, top, intensity[g]);
    }
    __syncthreads();   // sCnt=0 + up4 visible

    // ---- cull-compact survivor keys (order-free; rank sort follows) ----
    unsigned int m0 = __ballot_sync(0xFFFFFFFFu, kp[0]);
    unsigned int m1 = __ballot_sync(0xFFFFFFFFu, kp[1]);
    int cnt = __popc(m0) + __popc(m1);
    int base = 0;
    if (lane == 0 && cnt) base = atomicAdd(&sCnt, cnt);
    base = __shfl_sync(0xFFFFFFFFu, base, 0);
    const unsigned int ltmask = (1u << lane) - 1u;
    if (kp[0]) sk[base + __popc(m0 & ltmask)] = kk[0];
    if (kp[1]) sk[base + __popc(m0) + __popc(m1 & ltmask)] = kk[1];
    __syncthreads();

    const int Mc = sCnt;

    // ---- rank sort over the Mc survivors ----
    if (tid < Mc) {
        const unsigned long long mykey = sk[tid];
        int rank = 0;
        for (int j = 0; j < Mc; ++j) {
            rank += (sk[j] < mykey);   // broadcast LDS, unique keys
        }
        csp[rank] = up4[(int)(mykey & 0xFFFFFFFFull)];
    }
    __syncthreads();

    // ---- render: one pixel per thread ----
    const float fx = (float)tid;          // column (positions[:,1])

    float T = 1.0f;
    float A = 0.0f;

    #pragma unroll 4
    for (int j = 0; j < Mc; ++j) {
        const float4 P = csp[j];

        float dy  = fmaf(fx, P.x, P.y);        // (fx - py) * isy'
        float arg = fmaf(dy, -dy, P.z);        // top - dy'^2

        float ga;                              // == gauss * eff_w
        asm("ex2.approx.ftz.f32 %0, %1;" : "=f"(ga) : "f"(arg));

        float a  = fminf(ga, 0.99f);
        float ta = T * a;
        A = fmaf(ta, P.w, A);
        T -= ta;
    }

    out[blockIdx.x * W + tid] = A;
}

extern "C" void kernel_launch(void* const* d_in, const int* in_sizes, int n_in,
                              void* d_out, int out_size)
{
    const float* positions = (const float*)d_in[0];
    const float* scales    = (const float*)d_in[1];
    const float* opacity   = (const float*)d_in[2];
    const float* intensity = (const float*)d_in[3];
    const float* z_target  = (const float*)d_in[4];
    float* out = (float*)d_out;

    fused_kernel<<<GRID, TPB>>>(positions, scales, opacity, intensity,
                                z_target, out);
}